// round 1
// baseline (speedup 1.0000x reference)
#include <cuda_runtime.h>
#include <math.h>

#define D      2048
#define NS     8
#define BSZ    16384
#define TWOD   (2*D)

// output layout: read [B,D] | attn [B,8] | alpha [1] | new_state [8,D] | new_fast [8,D]
#define OFF_READ   0
#define OFF_ATTN   ((size_t)BSZ * D)
#define OFF_ALPHA  (OFF_ATTN + (size_t)BSZ * NS)
#define OFF_NS     (OFF_ALPHA + 1)
#define OFF_NF     (OFF_NS + (size_t)NS * D)

// ---------------- device scratch (static, no allocs) ----------------
__device__ float g_S[NS * D];      // state + fast
__device__ float g_Keq[NS * D];    // keys @ Wr
__device__ float g_cq[NS];         // keys @ br
__device__ float g_sWc[NS];        // S @ Wc[0, D:2D]
__device__ float g_M1[NS * D];     // attn.T @ (h + nm)
__device__ float g_G[NS * NS];     // attn.T @ attn
__device__ float g_asum[NS];       // sum_b attn
__device__ float g_sadd;           // sum_b sigmoid(ctrl0)
__device__ float g_R2[NS * D];     // G @ S
__device__ float g_delta[NS * D];  // partial delta (first two terms)

// ---------------- prep1: S = state + fast ; zero accumulators ----------------
__global__ void k_prep1(const float* __restrict__ state, const float* __restrict__ fast) {
    int i = blockIdx.x * blockDim.x + threadIdx.x;   // 0..16383
    g_S[i]     = state[i] + fast[i];
    g_Keq[i]   = 0.f;
    g_M1[i]    = 0.f;
    g_delta[i] = 0.f;
    if (i < NS * NS) g_G[i] = 0.f;
    if (i < NS)      g_asum[i] = 0.f;
    if (i == 0)      g_sadd = 0.f;
}

// ---------------- keq: Keq[s,i] = sum_j keys[s,j] * Wr[j,i] ----------------
// grid (8 i-chunks, 8 j-chunks), 256 threads. Accumulate via atomics into zeroed g_Keq.
__global__ void k_keq(const float* __restrict__ keys, const float* __restrict__ Wr) {
    __shared__ float ks[NS][256];
    int t = threadIdx.x;
    int j0 = blockIdx.y * 256;
    int i  = blockIdx.x * 256 + t;
    for (int idx = t; idx < NS * 256; idx += 256)
        ks[idx >> 8][idx & 255] = keys[(idx >> 8) * D + j0 + (idx & 255)];
    __syncthreads();
    float acc[NS];
#pragma unroll
    for (int s = 0; s < NS; s++) acc[s] = 0.f;
    for (int jj = 0; jj < 256; jj++) {
        float w = Wr[(size_t)(j0 + jj) * D + i];
#pragma unroll
        for (int s = 0; s < NS; s++) acc[s] += ks[s][jj] * w;
    }
#pragma unroll
    for (int s = 0; s < NS; s++) atomicAdd(&g_Keq[s * D + i], acc[s]);
}

// ---------------- prep2: cq[s] = keys[s].br ; sWc[s] = S[s].Wc[0,D:] ----------------
__global__ void k_prep2(const float* __restrict__ keys, const float* __restrict__ br,
                        const float* __restrict__ Wc) {
    __shared__ float rbuf[8];
    int s = blockIdx.x >> 1;
    int which = blockIdx.x & 1;
    const float* a = which ? (g_S + s * D) : (keys + s * D);
    const float* w = which ? (Wc + D) : br;
    float acc = 0.f;
    for (int i = threadIdx.x; i < D; i += 256) acc += a[i] * w[i];
#pragma unroll
    for (int off = 16; off; off >>= 1) acc += __shfl_xor_sync(0xffffffffu, acc, off);
    if ((threadIdx.x & 31) == 0) rbuf[threadIdx.x >> 5] = acc;
    __syncthreads();
    if (threadIdx.x == 0) {
        float tot = 0.f;
#pragma unroll
        for (int k = 0; k < 8; k++) tot += rbuf[k];
        if (which) g_sWc[s] = tot; else g_cq[s] = tot;
    }
}

// ---------------- fused per-row kernel ----------------
// Per row b: logits = h.Keq^T + cq ; softmax -> attn (write out);
// ctrl0 = h.Wc0 + attn.sWc + bc0 -> accumulate sigmoid;
// M1 += attn^T (h+nm) ; G += attn attn^T ; asum += attn.
__global__ __launch_bounds__(512, 1)
void k_fused(const float* __restrict__ h, const float* __restrict__ nm,
             const float* __restrict__ Wc, const float* __restrict__ bc,
             float* __restrict__ attn_out) {
    __shared__ float red[16][10];
    __shared__ float attn_sm[8];
    __shared__ float swc_sm[8];
    __shared__ float cq_sm[8];
    int t = threadIdx.x;
    int lane = t & 31, warp = t >> 5;
    if (t < 8) { swc_sm[t] = g_sWc[t]; cq_sm[t] = g_cq[t]; }

    // per-thread persistent state: my 4 columns (4*t .. 4*t+3)
    float keq[NS][4];
#pragma unroll
    for (int s = 0; s < NS; s++) {
        float4 v = ((const float4*)(g_Keq + s * D))[t];
        keq[s][0] = v.x; keq[s][1] = v.y; keq[s][2] = v.z; keq[s][3] = v.w;
    }
    float4 wv = ((const float4*)Wc)[t];   // Wc[0, 4t..4t+3]
    float wc0x = wv.x, wc0y = wv.y, wc0z = wv.z, wc0w = wv.w;
    float bc0 = bc[0];

    float m1[NS][4];
#pragma unroll
    for (int s = 0; s < NS; s++) { m1[s][0]=0.f; m1[s][1]=0.f; m1[s][2]=0.f; m1[s][3]=0.f; }
    float gl = 0.f, asl = 0.f, saddl = 0.f;
    __syncthreads();

    int per = (BSZ + gridDim.x - 1) / (int)gridDim.x;
    int b0 = blockIdx.x * per;
    int bend = min(b0 + per, BSZ);
    if (b0 >= bend) return;

    float4 h4 = ((const float4*)(h + (size_t)b0 * D))[t];
    float4 n4 = ((const float4*)(nm + (size_t)b0 * D))[t];

    for (int b = b0; b < bend; b++) {
        float4 hc = h4, nc = n4;
        if (b + 1 < bend) {  // prefetch next row
            h4 = ((const float4*)(h + (size_t)(b + 1) * D))[t];
            n4 = ((const float4*)(nm + (size_t)(b + 1) * D))[t];
        }
        float p[9];
#pragma unroll
        for (int s = 0; s < NS; s++)
            p[s] = keq[s][0]*hc.x + keq[s][1]*hc.y + keq[s][2]*hc.z + keq[s][3]*hc.w;
        p[8] = wc0x*hc.x + wc0y*hc.y + wc0z*hc.z + wc0w*hc.w;
#pragma unroll
        for (int off = 16; off; off >>= 1) {
#pragma unroll
            for (int v = 0; v < 9; v++)
                p[v] += __shfl_xor_sync(0xffffffffu, p[v], off);
        }
        if (lane == 0) {
#pragma unroll
            for (int v = 0; v < 9; v++) red[warp][v] = p[v];
        }
        __syncthreads();
        if (warp == 0) {
            float v = 0.f;
            if (lane < 9) {
#pragma unroll
                for (int w = 0; w < 16; w++) v += red[w][lane];
            }
            float hcv = __shfl_sync(0xffffffffu, v, 8);
            float logit = (lane < 8) ? (v + cq_sm[lane]) : -1e30f;
            float m = logit;
#pragma unroll
            for (int d = 1; d < 8; d <<= 1) m = fmaxf(m, __shfl_xor_sync(0xffffffffu, m, d));
            float e = (lane < 8) ? expf(logit - m) : 0.f;
            float se = e;
#pragma unroll
            for (int d = 1; d < 8; d <<= 1) se += __shfl_xor_sync(0xffffffffu, se, d);
            float a = e / se;
            float aw = (lane < 8) ? a * swc_sm[lane] : 0.f;
#pragma unroll
            for (int d = 1; d < 8; d <<= 1) aw += __shfl_xor_sync(0xffffffffu, aw, d);
            if (lane < 8) {
                attn_sm[lane] = a;
                attn_out[(size_t)b * NS + lane] = a;
                asl += a;
            }
            if (lane == 0) {
                float ctrl0 = hcv + aw + bc0;
                saddl += 1.f / (1.f + expf(-ctrl0));
            }
        }
        __syncthreads();
        float hn0 = hc.x + nc.x, hn1 = hc.y + nc.y, hn2 = hc.z + nc.z, hn3 = hc.w + nc.w;
#pragma unroll
        for (int s = 0; s < NS; s++) {
            float as = attn_sm[s];
            m1[s][0] += as * hn0; m1[s][1] += as * hn1;
            m1[s][2] += as * hn2; m1[s][3] += as * hn3;
        }
        if (t < 64) gl += attn_sm[t >> 3] * attn_sm[t & 7];
        // loop-end: attn_sm protected because next red/attn writes come after
        // all warps pass next __syncthreads()
    }
    __syncthreads();
#pragma unroll
    for (int s = 0; s < NS; s++) {
#pragma unroll
        for (int k = 0; k < 4; k++)
            atomicAdd(&g_M1[s * D + 4 * t + k], m1[s][k]);
    }
    if (t < 64) atomicAdd(&g_G[t], gl);
    if (t < 8)  atomicAdd(&g_asum[t], asl);
    if (t == 0) atomicAdd(&g_sadd, saddl);
}

// ---------------- read = attn @ S  (S held in registers per thread) ----------------
__global__ __launch_bounds__(256)
void k_read(const float* __restrict__ attn, float* __restrict__ out_read) {
    int t = threadIdx.x;   // thread owns cols 8t..8t+7
    float4 s0[NS], s1[NS];
#pragma unroll
    for (int s = 0; s < NS; s++) {
        s0[s] = ((const float4*)(g_S + s * D))[2 * t];
        s1[s] = ((const float4*)(g_S + s * D))[2 * t + 1];
    }
    int per = BSZ / (int)gridDim.x;
    int b0 = blockIdx.x * per;
    for (int b = b0; b < b0 + per; b++) {
        float4 a0 = ((const float4*)(attn + (size_t)b * NS))[0];
        float4 a1 = ((const float4*)(attn + (size_t)b * NS))[1];
        float aa[8] = {a0.x, a0.y, a0.z, a0.w, a1.x, a1.y, a1.z, a1.w};
        float4 r0 = {0.f,0.f,0.f,0.f}, r1 = {0.f,0.f,0.f,0.f};
#pragma unroll
        for (int s = 0; s < NS; s++) {
            r0.x += aa[s]*s0[s].x; r0.y += aa[s]*s0[s].y;
            r0.z += aa[s]*s0[s].z; r0.w += aa[s]*s0[s].w;
            r1.x += aa[s]*s1[s].x; r1.y += aa[s]*s1[s].y;
            r1.z += aa[s]*s1[s].z; r1.w += aa[s]*s1[s].w;
        }
        ((float4*)(out_read + (size_t)b * D))[2 * t]     = r0;
        ((float4*)(out_read + (size_t)b * D))[2 * t + 1] = r1;
    }
}

// ---------------- R2 = G @ S ----------------
__global__ void k_r2() {
    int idx = blockIdx.x * 256 + threadIdx.x;  // 16384
    int s = idx >> 11, i = idx & (D - 1);
    float acc = 0.f;
#pragma unroll
    for (int sp = 0; sp < NS; sp++) acc += g_G[s * NS + sp] * g_S[sp * D + i];
    g_R2[idx] = acc;
}

// ---------------- delta partials: [M1 | R2] @ Ww^T ----------------
// grid (8 o-chunks, 8 i-chunks of 512 over 4096), 256 threads (one o each)
__global__ __launch_bounds__(256)
void k_delta(const float* __restrict__ Ww) {
    __shared__ float u_sm[NS][512];
    int t = threadIdx.x;
    int i0 = blockIdx.y * 512;                  // 0..4095
    const float* U = (i0 < D) ? g_M1 : g_R2;
    int ui0 = (i0 < D) ? i0 : (i0 - D);
    for (int idx = t; idx < NS * 512; idx += 256)
        u_sm[idx >> 9][idx & 511] = U[(idx >> 9) * D + ui0 + (idx & 511)];
    __syncthreads();
    int o = blockIdx.x * 256 + t;
    float acc[NS];
#pragma unroll
    for (int s = 0; s < NS; s++) acc[s] = 0.f;
    const float* wrow = Ww + (size_t)o * TWOD + i0;
    for (int ii = 0; ii < 512; ii += 4) {
        float4 w = *(const float4*)(wrow + ii);
#pragma unroll
        for (int s = 0; s < NS; s++)
            acc[s] += u_sm[s][ii]*w.x + u_sm[s][ii+1]*w.y + u_sm[s][ii+2]*w.z + u_sm[s][ii+3]*w.w;
    }
#pragma unroll
    for (int s = 0; s < NS; s++) atomicAdd(&g_delta[s * D + o], acc[s]);
}

// ---------------- final: alpha, new_state, new_fast ----------------
__global__ void k_final(const float* __restrict__ bw, const float* __restrict__ state,
                        const float* __restrict__ fast, float* __restrict__ out) {
    int idx = blockIdx.x * 256 + threadIdx.x;   // 16384
    float mean = g_sadd * (1.f / (float)BSZ);
    float alpha = 0.02f + 0.98f * mean;
    alpha = fminf(fmaxf(alpha, 0.f), 1.f);      // ALPHA_BOOST = 1
    int s = idx >> 11, o = idx & (D - 1);
    float delta = g_delta[idx] + g_asum[s] * bw[o];
    out[OFF_NS + idx] = (1.f - alpha) * state[idx] + alpha * delta;
    out[OFF_NF + idx] = 0.95f * fast[idx] + 0.05f * delta;
    if (idx == 0) out[OFF_ALPHA] = alpha;
}

// ---------------- launch ----------------
extern "C" void kernel_launch(void* const* d_in, const int* in_sizes, int n_in,
                              void* d_out, int out_size) {
    const float* h     = (const float*)d_in[0];
    const float* nm    = (const float*)d_in[1];
    const float* keys  = (const float*)d_in[2];
    const float* Wr    = (const float*)d_in[3];
    const float* br    = (const float*)d_in[4];
    const float* Wc    = (const float*)d_in[5];
    const float* bc    = (const float*)d_in[6];
    const float* Ww    = (const float*)d_in[7];
    const float* bw    = (const float*)d_in[8];
    const float* state = (const float*)d_in[9];
    const float* fast  = (const float*)d_in[10];
    float* out = (float*)d_out;

    k_prep1<<<64, 256>>>(state, fast);
    k_keq<<<dim3(8, 8), 256>>>(keys, Wr);
    k_prep2<<<16, 256>>>(keys, br, Wc);
    k_fused<<<152, 512>>>(h, nm, Wc, bc, out + OFF_ATTN);
    k_read<<<512, 256>>>(out + OFF_ATTN, out + OFF_READ);
    k_r2<<<64, 256>>>();
    k_delta<<<dim3(8, 8), 256>>>(Ww);
    k_final<<<64, 256>>>(bw, state, fast, out);
}